// round 5
// baseline (speedup 1.0000x reference)
#include <cuda_runtime.h>
#include <cstdint>

// Problem constants
#define BS 4096
#define D  100
#define H  16
#define H2 (H/2)
#define P  2

// Blocking
#define BPT 7            // b's per thread
#define BQ  4            // b-groups per block
#define BTILE (BPT*BQ)   // 28 b's per block
#define NBLK ((BS + BTILE - 1) / BTILE)  // 147 blocks ~ 148 SMs, single wave
#define NTHR (BQ*D)      // 400 threads

typedef unsigned long long u64;

// Packed FMA: two independent IEEE fp32 FMAs per instruction (FFMA2). PTX-only on sm_103a.
#define FMA_F32X2(d, a, b, c) \
    asm("fma.rn.f32x2 %0, %1, %2, %3;" : "=l"(d) : "l"(a), "l"(b), "l"(c))
#define PACK_DUP_F32X2(out, v) \
    asm("mov.b64 %0, {%1, %1};" : "=l"(out) : "r"(__float_as_uint(v)))
#define UNPACK_F32X2(lo, hi, in) \
    asm("mov.b64 {%0, %1}, %2;" : "=r"(lo), "=r"(hi) : "l"(in))

// Transposed weights (t-contiguous for coalesced lane access), device globals (no alloc)
__device__ u64   g_W0p[D*H2*D];  // [j][i2][t] = pack(W0[t][2i2][j], W0[t][2i2+1][j])
__device__ float g_W1t[H*H*D];   // [i][j][t] = W1[t][i][j]
__device__ float g_W2t[P*H*D];   // [p][j][t] = W2[t][p][j]
__device__ float g_b0t[H*D];     // [i][t]
__device__ float g_b1t[H*D];     // [i][t]
__device__ float g_b2t[P*D];     // [p][t]

#define N_W0P (D*H2*D)           // 80000 packed elems
#define N_W1T (H*H*D)            // 25600
#define N_W2T (P*H*D)            // 3200
#define N_BT  (H*D)              // 1600
#define N_B2T (P*D)              // 200
#define N_TOTAL (N_W0P + N_W1T + N_W2T + N_BT + N_BT + N_B2T)  // 112200

__global__ void transpose_kernel(const float* __restrict__ W0, const float* __restrict__ b0,
                                 const float* __restrict__ W1, const float* __restrict__ b1,
                                 const float* __restrict__ W2, const float* __restrict__ b2) {
    int o = blockIdx.x * blockDim.x + threadIdx.x;
    if (o < N_W0P) {
        int j = o / (H2*D); int i2 = (o / D) % H2; int t = o % D;
        uint2 w;
        w.x = __float_as_uint(W0[(t*H + 2*i2    )*D + j]);
        w.y = __float_as_uint(W0[(t*H + 2*i2 + 1)*D + j]);
        g_W0p[o] = ((u64)w.y << 32) | (u64)w.x;
        return;
    }
    int o1 = o - N_W0P;
    if (o1 >= 0 && o1 < N_W1T) {
        int i = o1 / (H*D); int j = (o1 / D) % H; int t = o1 % D;
        g_W1t[o1] = W1[(t*H + i)*H + j];
        return;
    }
    int o2 = o1 - N_W1T;
    if (o2 >= 0 && o2 < N_W2T) {
        int p = o2 / (H*D); int j = (o2 / D) % H; int t = o2 % D;
        g_W2t[o2] = W2[(t*P + p)*H + j];
        return;
    }
    int o3 = o2 - N_W2T;
    if (o3 >= 0 && o3 < N_BT) { int i = o3 / D, t = o3 % D; g_b0t[o3] = b0[t*H + i]; return; }
    int o4 = o3 - N_BT;
    if (o4 >= 0 && o4 < N_BT) { int i = o4 / D, t = o4 % D; g_b1t[o4] = b1[t*H + i]; return; }
    int o5 = o4 - N_BT;
    if (o5 >= 0 && o5 < N_B2T) { int p = o5 / D, t = o5 % D; g_b2t[o5] = b2[t*P + p]; }
}

__global__ void __launch_bounds__(NTHR, 1)
fused_kernel(const float* __restrict__ x, const float* __restrict__ log_alpha,
             const float* __restrict__ noise, float* __restrict__ out) {
    __shared__ float xs[BTILE*D];   // x tile, rows match each thread's (clamped) b assignment

    const int tid = threadIdx.x;
    const int t   = tid % D;        // variable index; consecutive lanes -> consecutive t (coalesced)
    const int bq  = tid / D;        // b-group within block
    const int blk = blockIdx.x;

    // Cooperative x-tile load; per-group base clamped so all b's are in-bounds.
    for (int idx = tid; idx < BTILE*D; idx += NTHR) {
        int l = idx / D, j = idx % D;
        int src = min(blk*BTILE + (l / BPT)*BPT, BS - BPT) + (l % BPT);
        xs[idx] = x[src*D + j];
    }
    __syncthreads();

    const int cb = min(blk*BTILE + bq*BPT, BS - BPT);  // clamped base b (tail block recomputes dupes)
    const float* __restrict__ np   = noise + (size_t)cb * (D*D) + t;  // + k*D*D + j*D
    const float* __restrict__ lap  = log_alpha + t;                   // + j*D
    const u64*   __restrict__ w0p  = g_W0p + t;                       // + (j*H2 + i2)*D
    const float* __restrict__ xrow = xs + bq*BPT*D;                   // + k*D + j

    u64 acc2[BPT][H2];
    #pragma unroll
    for (int k = 0; k < BPT; k++)
        #pragma unroll
        for (int i2 = 0; i2 < H2; i2++) acc2[k][i2] = 0ull;

    // ---- Layer 0: masked per-variable matvec, packed f32x2 over i-pairs ----
    #pragma unroll 2
    for (int j = 0; j < D; j++) {
        float negla = -lap[(size_t)j*D];
        u64 w2[H2];
        #pragma unroll
        for (int i2 = 0; i2 < H2; i2++) w2[i2] = w0p[(size_t)(j*H2 + i2)*D];
        const bool adj = (j != t);   // no self-loop
        #pragma unroll
        for (int k = 0; k < BPT; k++) {
            float nz = np[(size_t)k*(D*D) + (size_t)j*D];
            float v  = (adj && (nz > negla)) ? xrow[k*D + j] : 0.f;
            u64 vv; PACK_DUP_F32X2(vv, v);
            #pragma unroll
            for (int i2 = 0; i2 < H2; i2++)
                FMA_F32X2(acc2[k][i2], w2[i2], vv, acc2[k][i2]);
        }
    }

    // Unpack, bias + leaky_relu (slope 0.01), branch-free
    float acc[BPT][H];
    #pragma unroll
    for (int k = 0; k < BPT; k++)
        #pragma unroll
        for (int i2 = 0; i2 < H2; i2++) {
            unsigned lo, hi;
            UNPACK_F32X2(lo, hi, acc2[k][i2]);
            acc[k][2*i2]   = __uint_as_float(lo);
            acc[k][2*i2+1] = __uint_as_float(hi);
        }
    #pragma unroll
    for (int i = 0; i < H; i++) {
        float bv = g_b0t[i*D + t];
        #pragma unroll
        for (int k = 0; k < BPT; k++) {
            float h = acc[k][i] + bv;
            acc[k][i] = fmaf(0.01f, fminf(h, 0.f), fmaxf(h, 0.f));
        }
    }

    // ---- Layer 1 + output layer fused per i-slice (keeps register pressure low) ----
    float o0[BPT], o1[BPT];
    {
        float b20 = g_b2t[t], b21 = g_b2t[D + t];
        #pragma unroll
        for (int k = 0; k < BPT; k++) { o0[k] = b20; o1[k] = b21; }
    }
    #pragma unroll
    for (int i = 0; i < H; i++) {
        float t1[BPT];
        float bv = g_b1t[i*D + t];
        #pragma unroll
        for (int k = 0; k < BPT; k++) t1[k] = bv;
        #pragma unroll
        for (int j = 0; j < H; j++) {
            float w1 = g_W1t[(i*H + j)*D + t];
            #pragma unroll
            for (int k = 0; k < BPT; k++) t1[k] = fmaf(w1, acc[k][j], t1[k]);
        }
        float w20 = g_W2t[i*D + t];
        float w21 = g_W2t[(H + i)*D + t];
        #pragma unroll
        for (int k = 0; k < BPT; k++) {
            float h = fmaf(0.01f, fminf(t1[k], 0.f), fmaxf(t1[k], 0.f));
            o0[k] = fmaf(w20, h, o0[k]);
            o1[k] = fmaf(w21, h, o1[k]);
        }
    }

    // Store out[b][t][0..1] as one float2 (coalesced across t lanes)
    float2* __restrict__ o2p = (float2*)out;
    #pragma unroll
    for (int k = 0; k < BPT; k++) {
        o2p[(size_t)(cb + k)*D + t] = make_float2(o0[k], o1[k]);
    }
}

extern "C" void kernel_launch(void* const* d_in, const int* in_sizes, int n_in,
                              void* d_out, int out_size) {
    const float* x  = (const float*)d_in[0];
    const float* la = (const float*)d_in[1];
    const float* nz = (const float*)d_in[2];
    const float* W0 = (const float*)d_in[3];
    const float* b0 = (const float*)d_in[4];
    const float* W1 = (const float*)d_in[5];
    const float* b1 = (const float*)d_in[6];
    const float* W2 = (const float*)d_in[7];
    const float* b2 = (const float*)d_in[8];

    transpose_kernel<<<(N_TOTAL + 255)/256, 256>>>(W0, b0, W1, b1, W2, b2);
    fused_kernel<<<NBLK, NTHR>>>(x, la, nz, (float*)d_out);
}